// round 13
// baseline (speedup 1.0000x reference)
#include <cuda_runtime.h>

#define BB    1024
#define LL    512
#define HH    128
#define GG    384
#define ATT   5
#define DLY   10
#define SCTAS 74
#define TPB   384
#define NPOS  (LL - ATT)

// static scratch (allocation-free rule)
__device__ float g_r [2][(size_t)BB * LL * HH];  // layer outputs (r0 then r1)
__device__ float g_gi[2][(size_t)BB * LL * GG];  // gi for layer1; reused as attend output c
__device__ float g_sp[2][BB * LL];               // s_p scores

// ---- packed f32x2 helpers ----
#define FMA_F32X2(d, a, b, c) \
    asm("fma.rn.f32x2 %0, %1, %2, %3;" : "=l"(d) : "l"(a), "l"(b), "l"(c))
#define PACK_F32X2(d, lo, hi) \
    asm("mov.b64 %0, {%1, %2};" : "=l"(d) : "r"(__float_as_uint(lo)), "r"(__float_as_uint(hi)))
#define UNPACK_F32X2(lo, hi, v) \
    asm("mov.b64 {%0, %1}, %2;" : "=r"(lo), "=r"(hi) : "l"(v))

__device__ __forceinline__ float sigf(float x) {
    return __fdividef(1.f, 1.f + __expf(-x));
}
__device__ __forceinline__ float tanh_f(float x) {
    x = fminf(fmaxf(x, -15.f), 15.f);
    float e = __expf(2.f * x);
    return __fdividef(e - 1.f, e + 1.f);
}

// pack 32 floats (one row's 32-wide k-chunk) into 16 b64 pairs
__device__ __forceinline__ void pack_row32(const float* __restrict__ w, unsigned long long* wp) {
#pragma unroll
    for (int k = 0; k < 8; k++) {
        float4 v = *(const float4*)(w + 4 * k);
        PACK_F32X2(wp[2 * k],     v.x, v.y);
        PACK_F32X2(wp[2 * k + 1], v.z, v.w);
    }
}

// k-split GEMV piece: thread (c = t&3) holds k-chunk [32c,32c+32) of rows r0..r0+3.
// sm_chunk = vector + 32*c (16B aligned). wp = 4 rows x 16 b64. Returns row (r0+c)'s
// FULL 128-dot after a 3-shuffle butterfly transpose-reduce over the 4-lane group.
__device__ __forceinline__ float dot32x4(const float* __restrict__ sm_chunk,
                                         const unsigned long long* __restrict__ wp,
                                         int c) {
    const ulonglong2* hv = (const ulonglong2*)sm_chunk;
    unsigned long long a0 = 0ull, a1 = 0ull, a2 = 0ull, a3 = 0ull;
#pragma unroll
    for (int k = 0; k < 8; k++) {
        ulonglong2 hk = hv[k];
        FMA_F32X2(a0, hk.x, wp[ 0 + 2 * k], a0);
        FMA_F32X2(a1, hk.x, wp[16 + 2 * k], a1);
        FMA_F32X2(a2, hk.x, wp[32 + 2 * k], a2);
        FMA_F32X2(a3, hk.x, wp[48 + 2 * k], a3);
        FMA_F32X2(a0, hk.y, wp[ 0 + 2 * k + 1], a0);
        FMA_F32X2(a1, hk.y, wp[16 + 2 * k + 1], a1);
        FMA_F32X2(a2, hk.y, wp[32 + 2 * k + 1], a2);
        FMA_F32X2(a3, hk.y, wp[48 + 2 * k + 1], a3);
    }
    unsigned int lo, hi;
    float s0, s1, s2, s3;
    UNPACK_F32X2(lo, hi, a0); s0 = __uint_as_float(lo) + __uint_as_float(hi);
    UNPACK_F32X2(lo, hi, a1); s1 = __uint_as_float(lo) + __uint_as_float(hi);
    UNPACK_F32X2(lo, hi, a2); s2 = __uint_as_float(lo) + __uint_as_float(hi);
    UNPACK_F32X2(lo, hi, a3); s3 = __uint_as_float(lo) + __uint_as_float(hi);
    // round 1 (xor 1): even lanes keep rows {0,2}, odd keep {1,3}
    float x1 = (c & 1) ? s0 : s1;
    float y1 = __shfl_xor_sync(0xffffffffu, x1, 1);
    if (c & 1) s1 += y1; else s0 += y1;
    float x2 = (c & 1) ? s2 : s3;
    float y2 = __shfl_xor_sync(0xffffffffu, x2, 1);
    if (c & 1) s3 += y2; else s2 += y2;
    // round 2 (xor 2): lane c ends with row r0+c
    float sa = (c & 1) ? s1 : s0;   // low valid row  (r0 + (c&1))
    float sb = (c & 1) ? s3 : s2;   // high valid row (r0 + (c&1) + 2)
    float x3 = (c & 2) ? sa : sb;
    float y3 = __shfl_xor_sync(0xffffffffu, x3, 2);
    return ((c & 2) ? sb : sa) + y3;
}

// ===== layer-0 GRU scan, both stacks (grid = 2*SCTAS) =====
__global__ void __launch_bounds__(TPB, 1) gru_l0_kernel(
    const float* __restrict__ x,
    const float* __restrict__ wih1, const float* __restrict__ whh1,
    const float* __restrict__ bih1, const float* __restrict__ bhh1,
    const float* __restrict__ wih2, const float* __restrict__ whh2,
    const float* __restrict__ bih2, const float* __restrict__ bhh2)
{
    int s    = blockIdx.x / SCTAS;
    int cidx = blockIdx.x % SCTAS;
    int b0 = cidx * BB / SCTAS, b1 = (cidx + 1) * BB / SCTAS;
    int nb = b1 - b0;
    const float* wih = s ? wih2 : wih1;
    const float* whh = s ? whh2 : whh1;
    const float* bih = s ? bih2 : bih1;
    const float* bhh = s ? bhh2 : bhh1;
    float* rout = g_r[s];
    int g = threadIdx.x;
    int c  = g & 3;
    int r0 = g & ~3;

    unsigned long long wp[64];
#pragma unroll
    for (int j = 0; j < 4; j++)
        pack_row32(whh + (r0 + j) * 128 + 32 * c, wp + 16 * j);
    float wi0 = wih[2 * g], wi1 = wih[2 * g + 1];
    float bi = bih[g], bh = bhh[g];

    __shared__ __align__(16) float h_sm[14][HH];
    __shared__ float grz [14][2 * HH];
    __shared__ float ginb[14][HH];
    __shared__ float ghnb[14][HH];
    for (int i = g; i < nb * HH; i += TPB) h_sm[i >> 7][i & 127] = 0.f;
    __syncthreads();

    for (int t = 0; t < LL; t++) {
        float x0 = __ldg(&x[((size_t)b0 * LL + t) * 2 + 0]);
        float x1 = __ldg(&x[((size_t)b0 * LL + t) * 2 + 1]);
        for (int b = 0; b < nb; b++) {
            float nx0 = 0.f, nx1 = 0.f;
            if (b + 1 < nb) {
                nx0 = __ldg(&x[((size_t)(b0 + b + 1) * LL + t) * 2 + 0]);
                nx1 = __ldg(&x[((size_t)(b0 + b + 1) * LL + t) * 2 + 1]);
            }
            float gh  = bh + dot32x4(h_sm[b] + 32 * c, wp, c);
            float giv = fmaf(wi1, x1, fmaf(wi0, x0, bi));
            if (g < 256) grz[b][g] = giv + gh;
            else { ginb[b][g - 256] = giv; ghnb[b][g - 256] = gh; }
            x0 = nx0; x1 = nx1;
        }
        __syncthreads();
        for (int i = g; i < nb * HH; i += TPB) {
            int b = i >> 7, j = i & 127;
            float r = sigf(grz[b][j]);
            float z = sigf(grz[b][HH + j]);
            float n = tanh_f(fmaf(r, ghnb[b][j], ginb[b][j]));
            float hv = fmaf(z, h_sm[b][j] - n, n);  // (1-z)*n + z*h
            h_sm[b][j] = hv;
            rout[((size_t)(b0 + b) * LL + t) * HH + j] = hv;
        }
        __syncthreads();
    }
}

// ===== gi = r0 @ W_ih_l1^T + b_ih_l1, both stacks =====
#define CHUNK 8
__global__ void __launch_bounds__(TPB, 1) gi_kernel(
    const float* __restrict__ wih1, const float* __restrict__ bih1,
    const float* __restrict__ wih2, const float* __restrict__ bih2)
{
    int s    = blockIdx.x / SCTAS;
    int cidx = blockIdx.x % SCTAS;
    int b0 = cidx * BB / SCTAS, b1 = (cidx + 1) * BB / SCTAS;
    const float* wih = s ? wih2 : wih1;
    const float* bih = s ? bih2 : bih1;
    const float* rin = g_r[s];
    float* gout = g_gi[s];
    int g = threadIdx.x;
    int c  = g & 3;
    int r0 = g & ~3;

    unsigned long long wp[64];
#pragma unroll
    for (int j = 0; j < 4; j++)
        pack_row32(wih + (r0 + j) * 128 + 32 * c, wp + 16 * j);
    float bi = bih[g];

    __shared__ __align__(16) float rbuf[2][CHUNK][HH];
    size_t p0   = (size_t)b0 * LL;
    size_t pend = (size_t)b1 * LL;

    if (g < CHUNK * HH / 4)
        ((float4*)rbuf[0])[g] = ((const float4*)(rin + p0 * HH))[g];
    __syncthreads();

    int cur = 0;
    for (size_t p = p0; p < pend; p += CHUNK) {
        float4 v = make_float4(0.f, 0.f, 0.f, 0.f);
        bool hasnext = (p + CHUNK) < pend;
        if (hasnext && g < CHUNK * HH / 4)
            v = ((const float4*)(rin + (p + CHUNK) * HH))[g];
#pragma unroll
        for (int q = 0; q < CHUNK; q++)
            gout[(p + q) * GG + g] = bi + dot32x4(rbuf[cur][q] + 32 * c, wp, c);
        if (hasnext && g < CHUNK * HH / 4)
            ((float4*)rbuf[cur ^ 1])[g] = v;
        __syncthreads();
        cur ^= 1;
    }
}

// ===== layer-1 GRU scan (gi streamed from gmem), both stacks =====
__global__ void __launch_bounds__(TPB, 1) gru_l1_kernel(
    const float* __restrict__ whh1, const float* __restrict__ bhh1,
    const float* __restrict__ whh2, const float* __restrict__ bhh2)
{
    int s    = blockIdx.x / SCTAS;
    int cidx = blockIdx.x % SCTAS;
    int b0 = cidx * BB / SCTAS, b1 = (cidx + 1) * BB / SCTAS;
    int nb = b1 - b0;
    const float* whh = s ? whh2 : whh1;
    const float* bhh = s ? bhh2 : bhh1;
    const float* gbuf = g_gi[s];
    float* rout = g_r[s];   // r0 dead after gi_kernel; overwrite with r1
    int g = threadIdx.x;
    int c  = g & 3;
    int r0 = g & ~3;

    unsigned long long wp[64];
#pragma unroll
    for (int j = 0; j < 4; j++)
        pack_row32(whh + (r0 + j) * 128 + 32 * c, wp + 16 * j);
    float bh = bhh[g];

    __shared__ __align__(16) float h_sm[14][HH];
    __shared__ float grz [14][2 * HH];
    __shared__ float ginb[14][HH];
    __shared__ float ghnb[14][HH];
    for (int i = g; i < nb * HH; i += TPB) h_sm[i >> 7][i & 127] = 0.f;
    __syncthreads();

    for (int t = 0; t < LL; t++) {
        float giv = __ldg(&gbuf[((size_t)b0 * LL + t) * GG + g]);
        for (int b = 0; b < nb; b++) {
            float gnxt = 0.f;
            if (b + 1 < nb)
                gnxt = __ldg(&gbuf[((size_t)(b0 + b + 1) * LL + t) * GG + g]);
            float gh = bh + dot32x4(h_sm[b] + 32 * c, wp, c);
            if (g < 256) grz[b][g] = giv + gh;
            else { ginb[b][g - 256] = giv; ghnb[b][g - 256] = gh; }
            giv = gnxt;
        }
        __syncthreads();
        for (int i = g; i < nb * HH; i += TPB) {
            int b = i >> 7, j = i & 127;
            float r = sigf(grz[b][j]);
            float z = sigf(grz[b][HH + j]);
            float n = tanh_f(fmaf(r, ghnb[b][j], ginb[b][j]));
            float hv = fmaf(z, h_sm[b][j] - n, n);
            h_sm[b][j] = hv;
            rout[((size_t)(b0 + b) * LL + t) * HH + j] = hv;
        }
        __syncthreads();
    }
}

// ===== s_p = r1 @ w_a[0, H:2H]  (s_h and b_a cancel in the 5-way softmax) =====
__global__ void sp_kernel(const float* __restrict__ wa) {
    int s = blockIdx.x >> 10;
    int b = blockIdx.x & 1023;
    int w = threadIdx.x >> 5;
    int l = threadIdx.x & 31;
    float4 wv = *(const float4*)(wa + HH + 4 * l);
    const float* rbase = g_r[s] + (size_t)b * LL * HH;
    for (int t = w; t < LL; t += 8) {
        float4 rv = *(const float4*)(rbase + (size_t)t * HH + 4 * l);
        float p = rv.x * wv.x + rv.y * wv.y + rv.z * wv.z + rv.w * wv.w;
        p += __shfl_xor_sync(0xffffffffu, p, 16);
        p += __shfl_xor_sync(0xffffffffu, p, 8);
        p += __shfl_xor_sync(0xffffffffu, p, 4);
        p += __shfl_xor_sync(0xffffffffu, p, 2);
        p += __shfl_xor_sync(0xffffffffu, p, 1);
        if (l == 0) g_sp[s][b * LL + t] = p;
    }
}

// ===== softmax(5) + context + combine matvecs =====
// rows rho = half*128 + j; thread t ends owning row t of the 256-row combine.
__global__ void __launch_bounds__(256, 1) attend_kernel(
    const float* __restrict__ wc, const float* __restrict__ bc)
{
    int s = blockIdx.x >> 10;
    int b = blockIdx.x & 1023;
    int t4   = threadIdx.x;
    int j    = t4 & 127;
    int half = t4 >> 7;
    int c    = t4 & 3;
    int rho0 = t4 & ~3;          // 4-row group (never crosses the half boundary)
    int hf   = rho0 >> 7;        // == half
    int jj0  = rho0 & 127;

    unsigned long long wp[64];
#pragma unroll
    for (int jr = 0; jr < 4; jr++)
        pack_row32(wc + (jj0 + jr) * 256 + hf * 128 + 32 * c, wp + 16 * jr);

    const float* rbase = g_r[s] + (size_t)b * LL * HH;
    const float* spb   = g_sp[s] + b * LL;
    float* cbase = g_gi[s] + (size_t)b * LL * HH;  // reuse gi buffer as c output

    __shared__ __align__(16) float c_sm[4][HH];
    __shared__ __align__(16) float r_sm[4][HH];
    __shared__ float part[4][2 * HH];

    for (int i0 = 0; i0 < NPOS; i0 += 4) {
#pragma unroll
        for (int qq = 0; qq < 2; qq++) {
            int q = half * 2 + qq;
            int i = i0 + q;
            if (i < NPOS) {
                float e0 = spb[i], e1 = spb[i + 1], e2 = spb[i + 2], e3 = spb[i + 3], e4 = spb[i + 4];
                float m = fmaxf(fmaxf(fmaxf(e0, e1), fmaxf(e2, e3)), e4);
                float w0 = __expf(e0 - m), w1 = __expf(e1 - m), w2 = __expf(e2 - m);
                float w3 = __expf(e3 - m), w4 = __expf(e4 - m);
                float inv = __fdividef(1.f, w0 + w1 + w2 + w3 + w4);
                float cx = w0 * rbase[(size_t)(i + 0) * HH + j] + w1 * rbase[(size_t)(i + 1) * HH + j]
                         + w2 * rbase[(size_t)(i + 2) * HH + j] + w3 * rbase[(size_t)(i + 3) * HH + j]
                         + w4 * rbase[(size_t)(i + 4) * HH + j];
                c_sm[q][j] = cx * inv;
                r_sm[q][j] = rbase[(size_t)(i + ATT) * HH + j];
            }
        }
        __syncthreads();
#pragma unroll
        for (int q = 0; q < 4; q++) {
            if (i0 + q < NPOS) {
                const float* src = hf ? r_sm[q] : c_sm[q];
                part[q][t4] = dot32x4(src + 32 * c, wp, c);
            }
        }
        __syncthreads();
        for (int it = t4; it < 4 * HH; it += 256) {
            int q = it >> 7, jjw = it & 127;
            int i = i0 + q;
            if (i < NPOS)
                cbase[(size_t)(i + ATT) * HH + jjw] = part[q][jjw] + part[q][HH + jjw] + bc[jjw];
        }
        __syncthreads();
    }
}

// ===== dec = c1.wo[:H] + c2[min(t+DLY,L-1)].wo[H:] + b_o ; sigmoid =====
__global__ void final_kernel(const float* __restrict__ wo, const float* __restrict__ bo,
                             float* __restrict__ out)
{
    int w = threadIdx.x >> 5;
    int l = threadIdx.x & 31;
    int o = blockIdx.x * 8 + w;
    int b = o >> 9;
    int t = o & 511;
    const float* c1 = (t < ATT) ? (g_r[0] + ((size_t)b * LL + t) * HH)
                                : (g_gi[0] + ((size_t)b * LL + t) * HH);
    int t2 = t + DLY; if (t2 > LL - 1) t2 = LL - 1;   // t2 >= DLY > ATT: always attend region
    const float* c2 = g_gi[1] + ((size_t)b * LL + t2) * HH;

    float4 a = *(const float4*)(c1 + 4 * l);
    float4 u = *(const float4*)(wo + 4 * l);
    float4 cc = *(const float4*)(c2 + 4 * l);
    float4 v = *(const float4*)(wo + HH + 4 * l);
    float p = a.x * u.x + a.y * u.y + a.z * u.z + a.w * u.w
            + cc.x * v.x + cc.y * v.y + cc.z * v.z + cc.w * v.w;
    p += __shfl_xor_sync(0xffffffffu, p, 16);
    p += __shfl_xor_sync(0xffffffffu, p, 8);
    p += __shfl_xor_sync(0xffffffffu, p, 4);
    p += __shfl_xor_sync(0xffffffffu, p, 2);
    p += __shfl_xor_sync(0xffffffffu, p, 1);
    if (l == 0) out[o] = sigf(p + bo[0]);
}

extern "C" void kernel_launch(void* const* d_in, const int* in_sizes, int n_in,
                              void* d_out, int out_size) {
    const float* x = (const float*)d_in[0];
    const float *wih1_0 = (const float*)d_in[1],  *whh1_0 = (const float*)d_in[2];
    const float *bih1_0 = (const float*)d_in[3],  *bhh1_0 = (const float*)d_in[4];
    const float *wih1_1 = (const float*)d_in[5],  *whh1_1 = (const float*)d_in[6];
    const float *bih1_1 = (const float*)d_in[7],  *bhh1_1 = (const float*)d_in[8];
    const float *wih2_0 = (const float*)d_in[9],  *whh2_0 = (const float*)d_in[10];
    const float *bih2_0 = (const float*)d_in[11], *bhh2_0 = (const float*)d_in[12];
    const float *wih2_1 = (const float*)d_in[13], *whh2_1 = (const float*)d_in[14];
    const float *bih2_1 = (const float*)d_in[15], *bhh2_1 = (const float*)d_in[16];
    const float *wa = (const float*)d_in[17];
    const float *wc = (const float*)d_in[19], *bc = (const float*)d_in[20];
    const float *wo = (const float*)d_in[21], *bo = (const float*)d_in[22];

    gru_l0_kernel<<<2 * SCTAS, TPB>>>(x, wih1_0, whh1_0, bih1_0, bhh1_0,
                                      wih2_0, whh2_0, bih2_0, bhh2_0);
    gi_kernel<<<2 * SCTAS, TPB>>>(wih1_1, bih1_1, wih2_1, bih2_1);
    gru_l1_kernel<<<2 * SCTAS, TPB>>>(whh1_1, bhh1_1, whh2_1, bhh2_1);
    sp_kernel<<<2 * BB, 256>>>(wa);
    attend_kernel<<<2 * BB, 256>>>(wc, bc);
    final_kernel<<<(BB * LL) / 8, 256>>>(wo, bo, (float*)d_out);
}

// round 14
// speedup vs baseline: 1.9788x; 1.9788x over previous
#include <cuda_runtime.h>

#define BB    1024
#define LL    512
#define HH    128
#define GG    384
#define ATT   5
#define DLY   10
#define SCTAS 74
#define TPB   384
#define NPOS  (LL - ATT)

// static scratch (allocation-free rule)
__device__ float g_r [2][(size_t)BB * LL * HH];  // layer outputs (r0 then r1)
__device__ float g_gi[2][(size_t)BB * LL * GG];  // gi for layer1; reused as attend output c
__device__ float g_sp[2][BB * LL];               // s_p scores

// ---- packed f32x2 helpers ----
#define FMA_F32X2(d, a, b, c) \
    asm("fma.rn.f32x2 %0, %1, %2, %3;" : "=l"(d) : "l"(a), "l"(b), "l"(c))
#define PACK_F32X2(d, lo, hi) \
    asm("mov.b64 %0, {%1, %2};" : "=l"(d) : "r"(__float_as_uint(lo)), "r"(__float_as_uint(hi)))
#define UNPACK_F32X2(lo, hi, v) \
    asm("mov.b64 {%0, %1}, %2;" : "=r"(lo), "=r"(hi) : "l"(v))

__device__ __forceinline__ float sigf(float x) {
    return __fdividef(1.f, 1.f + __expf(-x));
}
__device__ __forceinline__ float tanh_f(float x) {
    x = fminf(fmaxf(x, -15.f), 15.f);
    float e = __expf(2.f * x);
    return __fdividef(e - 1.f, e + 1.f);
}

// pack one row's INTERLEAVED 32-float k-subset (float4 chunks at positions 16k'+4c)
__device__ __forceinline__ void pack_row32i(const float* __restrict__ wrow, int c,
                                            unsigned long long* wp) {
#pragma unroll
    for (int k = 0; k < 8; k++) {
        float4 v = *(const float4*)(wrow + 16 * k + 4 * c);
        PACK_F32X2(wp[2 * k],     v.x, v.y);
        PACK_F32X2(wp[2 * k + 1], v.z, v.w);
    }
}

// Interleaved k-split GEMV piece: thread (c = t&3) holds k-chunks {16k'+4c} of rows r0..r0+3.
// Lane group reads bytes 64k'+{0,16,32,48}: conflict-free, broadcast across the 8 groups.
// Returns row (r0+c)'s FULL 128-dot after a 3-shuffle butterfly transpose-reduce.
__device__ __forceinline__ float dot32x4(const float* __restrict__ sm,
                                         const unsigned long long* __restrict__ wp,
                                         int c) {
    const ulonglong2* hv = (const ulonglong2*)sm;
    unsigned long long a0 = 0ull, a1 = 0ull, a2 = 0ull, a3 = 0ull;
#pragma unroll
    for (int k = 0; k < 8; k++) {
        ulonglong2 hk = hv[4 * k + c];
        FMA_F32X2(a0, hk.x, wp[ 0 + 2 * k], a0);
        FMA_F32X2(a1, hk.x, wp[16 + 2 * k], a1);
        FMA_F32X2(a2, hk.x, wp[32 + 2 * k], a2);
        FMA_F32X2(a3, hk.x, wp[48 + 2 * k], a3);
        FMA_F32X2(a0, hk.y, wp[ 0 + 2 * k + 1], a0);
        FMA_F32X2(a1, hk.y, wp[16 + 2 * k + 1], a1);
        FMA_F32X2(a2, hk.y, wp[32 + 2 * k + 1], a2);
        FMA_F32X2(a3, hk.y, wp[48 + 2 * k + 1], a3);
    }
    unsigned int lo, hi;
    float s0, s1, s2, s3;
    UNPACK_F32X2(lo, hi, a0); s0 = __uint_as_float(lo) + __uint_as_float(hi);
    UNPACK_F32X2(lo, hi, a1); s1 = __uint_as_float(lo) + __uint_as_float(hi);
    UNPACK_F32X2(lo, hi, a2); s2 = __uint_as_float(lo) + __uint_as_float(hi);
    UNPACK_F32X2(lo, hi, a3); s3 = __uint_as_float(lo) + __uint_as_float(hi);
    // round 1 (xor 1): even lanes keep rows {0,2}, odd keep {1,3}
    float x1 = (c & 1) ? s0 : s1;
    float y1 = __shfl_xor_sync(0xffffffffu, x1, 1);
    if (c & 1) s1 += y1; else s0 += y1;
    float x2 = (c & 1) ? s2 : s3;
    float y2 = __shfl_xor_sync(0xffffffffu, x2, 1);
    if (c & 1) s3 += y2; else s2 += y2;
    // round 2 (xor 2): lane c ends with row r0+c
    float sa = (c & 1) ? s1 : s0;
    float sb = (c & 1) ? s3 : s2;
    float x3 = (c & 2) ? sa : sb;
    float y3 = __shfl_xor_sync(0xffffffffu, x3, 2);
    return ((c & 2) ? sb : sa) + y3;
}

// ===== layer-0 GRU scan, both stacks (grid = 2*SCTAS) =====
__global__ void __launch_bounds__(TPB, 1) gru_l0_kernel(
    const float* __restrict__ x,
    const float* __restrict__ wih1, const float* __restrict__ whh1,
    const float* __restrict__ bih1, const float* __restrict__ bhh1,
    const float* __restrict__ wih2, const float* __restrict__ whh2,
    const float* __restrict__ bih2, const float* __restrict__ bhh2)
{
    int s    = blockIdx.x / SCTAS;
    int cidx = blockIdx.x % SCTAS;
    int b0 = cidx * BB / SCTAS, b1 = (cidx + 1) * BB / SCTAS;
    int nb = b1 - b0;
    const float* wih = s ? wih2 : wih1;
    const float* whh = s ? whh2 : whh1;
    const float* bih = s ? bih2 : bih1;
    const float* bhh = s ? bhh2 : bhh1;
    float* rout = g_r[s];
    int g = threadIdx.x;
    int c  = g & 3;
    int r0 = g & ~3;

    unsigned long long wp[64];
#pragma unroll
    for (int j = 0; j < 4; j++)
        pack_row32i(whh + (r0 + j) * 128, c, wp + 16 * j);
    float wi0 = wih[2 * g], wi1 = wih[2 * g + 1];
    float bi = bih[g], bh = bhh[g];

    __shared__ __align__(16) float h_sm[14][HH];
    __shared__ float grz [14][2 * HH];
    __shared__ float ginb[14][HH];
    __shared__ float ghnb[14][HH];
    for (int i = g; i < nb * HH; i += TPB) h_sm[i >> 7][i & 127] = 0.f;
    __syncthreads();

    for (int t = 0; t < LL; t++) {
        float x0 = __ldg(&x[((size_t)b0 * LL + t) * 2 + 0]);
        float x1 = __ldg(&x[((size_t)b0 * LL + t) * 2 + 1]);
        for (int b = 0; b < nb; b++) {
            float nx0 = 0.f, nx1 = 0.f;
            if (b + 1 < nb) {
                nx0 = __ldg(&x[((size_t)(b0 + b + 1) * LL + t) * 2 + 0]);
                nx1 = __ldg(&x[((size_t)(b0 + b + 1) * LL + t) * 2 + 1]);
            }
            float gh  = bh + dot32x4(h_sm[b], wp, c);
            float giv = fmaf(wi1, x1, fmaf(wi0, x0, bi));
            if (g < 256) grz[b][g] = giv + gh;
            else { ginb[b][g - 256] = giv; ghnb[b][g - 256] = gh; }
            x0 = nx0; x1 = nx1;
        }
        __syncthreads();
        for (int i = g; i < nb * HH; i += TPB) {
            int b = i >> 7, j = i & 127;
            float r = sigf(grz[b][j]);
            float z = sigf(grz[b][HH + j]);
            float n = tanh_f(fmaf(r, ghnb[b][j], ginb[b][j]));
            float hv = fmaf(z, h_sm[b][j] - n, n);  // (1-z)*n + z*h
            h_sm[b][j] = hv;
            rout[((size_t)(b0 + b) * LL + t) * HH + j] = hv;
        }
        __syncthreads();
    }
}

// ===== gi = r0 @ W_ih_l1^T + b_ih_l1, both stacks =====
#define CHUNK 8
__global__ void __launch_bounds__(TPB, 1) gi_kernel(
    const float* __restrict__ wih1, const float* __restrict__ bih1,
    const float* __restrict__ wih2, const float* __restrict__ bih2)
{
    int s    = blockIdx.x / SCTAS;
    int cidx = blockIdx.x % SCTAS;
    int b0 = cidx * BB / SCTAS, b1 = (cidx + 1) * BB / SCTAS;
    const float* wih = s ? wih2 : wih1;
    const float* bih = s ? bih2 : bih1;
    const float* rin = g_r[s];
    float* gout = g_gi[s];
    int g = threadIdx.x;
    int c  = g & 3;
    int r0 = g & ~3;

    unsigned long long wp[64];
#pragma unroll
    for (int j = 0; j < 4; j++)
        pack_row32i(wih + (r0 + j) * 128, c, wp + 16 * j);
    float bi = bih[g];

    __shared__ __align__(16) float rbuf[2][CHUNK][HH];
    size_t p0   = (size_t)b0 * LL;
    size_t pend = (size_t)b1 * LL;

    if (g < CHUNK * HH / 4)
        ((float4*)rbuf[0])[g] = ((const float4*)(rin + p0 * HH))[g];
    __syncthreads();

    int cur = 0;
    for (size_t p = p0; p < pend; p += CHUNK) {
        float4 v = make_float4(0.f, 0.f, 0.f, 0.f);
        bool hasnext = (p + CHUNK) < pend;
        if (hasnext && g < CHUNK * HH / 4)
            v = ((const float4*)(rin + (p + CHUNK) * HH))[g];
#pragma unroll
        for (int q = 0; q < CHUNK; q++)
            gout[(p + q) * GG + g] = bi + dot32x4(rbuf[cur][q], wp, c);
        if (hasnext && g < CHUNK * HH / 4)
            ((float4*)rbuf[cur ^ 1])[g] = v;
        __syncthreads();
        cur ^= 1;
    }
}

// ===== layer-1 GRU scan (gi streamed from gmem), both stacks =====
__global__ void __launch_bounds__(TPB, 1) gru_l1_kernel(
    const float* __restrict__ whh1, const float* __restrict__ bhh1,
    const float* __restrict__ whh2, const float* __restrict__ bhh2)
{
    int s    = blockIdx.x / SCTAS;
    int cidx = blockIdx.x % SCTAS;
    int b0 = cidx * BB / SCTAS, b1 = (cidx + 1) * BB / SCTAS;
    int nb = b1 - b0;
    const float* whh = s ? whh2 : whh1;
    const float* bhh = s ? bhh2 : bhh1;
    const float* gbuf = g_gi[s];
    float* rout = g_r[s];   // r0 dead after gi_kernel; overwrite with r1
    int g = threadIdx.x;
    int c  = g & 3;
    int r0 = g & ~3;

    unsigned long long wp[64];
#pragma unroll
    for (int j = 0; j < 4; j++)
        pack_row32i(whh + (r0 + j) * 128, c, wp + 16 * j);
    float bh = bhh[g];

    __shared__ __align__(16) float h_sm[14][HH];
    __shared__ float grz [14][2 * HH];
    __shared__ float ginb[14][HH];
    __shared__ float ghnb[14][HH];
    for (int i = g; i < nb * HH; i += TPB) h_sm[i >> 7][i & 127] = 0.f;
    __syncthreads();

    for (int t = 0; t < LL; t++) {
        float giv = __ldg(&gbuf[((size_t)b0 * LL + t) * GG + g]);
        for (int b = 0; b < nb; b++) {
            float gnxt = 0.f;
            if (b + 1 < nb)
                gnxt = __ldg(&gbuf[((size_t)(b0 + b + 1) * LL + t) * GG + g]);
            float gh = bh + dot32x4(h_sm[b], wp, c);
            if (g < 256) grz[b][g] = giv + gh;
            else { ginb[b][g - 256] = giv; ghnb[b][g - 256] = gh; }
            giv = gnxt;
        }
        __syncthreads();
        for (int i = g; i < nb * HH; i += TPB) {
            int b = i >> 7, j = i & 127;
            float r = sigf(grz[b][j]);
            float z = sigf(grz[b][HH + j]);
            float n = tanh_f(fmaf(r, ghnb[b][j], ginb[b][j]));
            float hv = fmaf(z, h_sm[b][j] - n, n);
            h_sm[b][j] = hv;
            rout[((size_t)(b0 + b) * LL + t) * HH + j] = hv;
        }
        __syncthreads();
    }
}

// ===== s_p = r1 @ w_a[0, H:2H]  (s_h and b_a cancel in the 5-way softmax) =====
__global__ void sp_kernel(const float* __restrict__ wa) {
    int s = blockIdx.x >> 10;
    int b = blockIdx.x & 1023;
    int w = threadIdx.x >> 5;
    int l = threadIdx.x & 31;
    float4 wv = *(const float4*)(wa + HH + 4 * l);
    const float* rbase = g_r[s] + (size_t)b * LL * HH;
    for (int t = w; t < LL; t += 8) {
        float4 rv = *(const float4*)(rbase + (size_t)t * HH + 4 * l);
        float p = rv.x * wv.x + rv.y * wv.y + rv.z * wv.z + rv.w * wv.w;
        p += __shfl_xor_sync(0xffffffffu, p, 16);
        p += __shfl_xor_sync(0xffffffffu, p, 8);
        p += __shfl_xor_sync(0xffffffffu, p, 4);
        p += __shfl_xor_sync(0xffffffffu, p, 2);
        p += __shfl_xor_sync(0xffffffffu, p, 1);
        if (l == 0) g_sp[s][b * LL + t] = p;
    }
}

// ===== softmax(5) + context + combine matvecs =====
// rows rho = half*128 + j; thread t ends owning row t of the 256-row combine.
__global__ void __launch_bounds__(256, 1) attend_kernel(
    const float* __restrict__ wc, const float* __restrict__ bc)
{
    int s = blockIdx.x >> 10;
    int b = blockIdx.x & 1023;
    int t4   = threadIdx.x;
    int j    = t4 & 127;
    int half = t4 >> 7;
    int c    = t4 & 3;
    int rho0 = t4 & ~3;          // 4-row group (never crosses the half boundary)
    int hf   = rho0 >> 7;        // == half
    int jj0  = rho0 & 127;

    unsigned long long wp[64];
#pragma unroll
    for (int jr = 0; jr < 4; jr++)
        pack_row32i(wc + (jj0 + jr) * 256 + hf * 128, c, wp + 16 * jr);

    const float* rbase = g_r[s] + (size_t)b * LL * HH;
    const float* spb   = g_sp[s] + b * LL;
    float* cbase = g_gi[s] + (size_t)b * LL * HH;  // reuse gi buffer as c output

    __shared__ __align__(16) float c_sm[4][HH];
    __shared__ __align__(16) float r_sm[4][HH];
    __shared__ float part[4][2 * HH];

    for (int i0 = 0; i0 < NPOS; i0 += 4) {
#pragma unroll
        for (int qq = 0; qq < 2; qq++) {
            int q = half * 2 + qq;
            int i = i0 + q;
            if (i < NPOS) {
                float e0 = spb[i], e1 = spb[i + 1], e2 = spb[i + 2], e3 = spb[i + 3], e4 = spb[i + 4];
                float m = fmaxf(fmaxf(fmaxf(e0, e1), fmaxf(e2, e3)), e4);
                float w0 = __expf(e0 - m), w1 = __expf(e1 - m), w2 = __expf(e2 - m);
                float w3 = __expf(e3 - m), w4 = __expf(e4 - m);
                float inv = __fdividef(1.f, w0 + w1 + w2 + w3 + w4);
                float cx = w0 * rbase[(size_t)(i + 0) * HH + j] + w1 * rbase[(size_t)(i + 1) * HH + j]
                         + w2 * rbase[(size_t)(i + 2) * HH + j] + w3 * rbase[(size_t)(i + 3) * HH + j]
                         + w4 * rbase[(size_t)(i + 4) * HH + j];
                c_sm[q][j] = cx * inv;
                r_sm[q][j] = rbase[(size_t)(i + ATT) * HH + j];
            }
        }
        __syncthreads();
#pragma unroll
        for (int q = 0; q < 4; q++) {
            if (i0 + q < NPOS) {
                const float* src = hf ? r_sm[q] : c_sm[q];
                part[q][t4] = dot32x4(src, wp, c);
            }
        }
        __syncthreads();
        for (int it = t4; it < 4 * HH; it += 256) {
            int q = it >> 7, jjw = it & 127;
            int i = i0 + q;
            if (i < NPOS)
                cbase[(size_t)(i + ATT) * HH + jjw] = part[q][jjw] + part[q][HH + jjw] + bc[jjw];
        }
        __syncthreads();
    }
}

// ===== dec = c1.wo[:H] + c2[min(t+DLY,L-1)].wo[H:] + b_o ; sigmoid =====
__global__ void final_kernel(const float* __restrict__ wo, const float* __restrict__ bo,
                             float* __restrict__ out)
{
    int w = threadIdx.x >> 5;
    int l = threadIdx.x & 31;
    int o = blockIdx.x * 8 + w;
    int b = o >> 9;
    int t = o & 511;
    const float* c1 = (t < ATT) ? (g_r[0] + ((size_t)b * LL + t) * HH)
                                : (g_gi[0] + ((size_t)b * LL + t) * HH);
    int t2 = t + DLY; if (t2 > LL - 1) t2 = LL - 1;   // t2 >= DLY > ATT: always attend region
    const float* c2 = g_gi[1] + ((size_t)b * LL + t2) * HH;

    float4 a = *(const float4*)(c1 + 4 * l);
    float4 u = *(const float4*)(wo + 4 * l);
    float4 cc = *(const float4*)(c2 + 4 * l);
    float4 v = *(const float4*)(wo + HH + 4 * l);
    float p = a.x * u.x + a.y * u.y + a.z * u.z + a.w * u.w
            + cc.x * v.x + cc.y * v.y + cc.z * v.z + cc.w * v.w;
    p += __shfl_xor_sync(0xffffffffu, p, 16);
    p += __shfl_xor_sync(0xffffffffu, p, 8);
    p += __shfl_xor_sync(0xffffffffu, p, 4);
    p += __shfl_xor_sync(0xffffffffu, p, 2);
    p += __shfl_xor_sync(0xffffffffu, p, 1);
    if (l == 0) out[o] = sigf(p + bo[0]);
}

extern "C" void kernel_launch(void* const* d_in, const int* in_sizes, int n_in,
                              void* d_out, int out_size) {
    const float* x = (const float*)d_in[0];
    const float *wih1_0 = (const float*)d_in[1],  *whh1_0 = (const float*)d_in[2];
    const float *bih1_0 = (const float*)d_in[3],  *bhh1_0 = (const float*)d_in[4];
    const float *wih1_1 = (const float*)d_in[5],  *whh1_1 = (const float*)d_in[6];
    const float *bih1_1 = (const float*)d_in[7],  *bhh1_1 = (const float*)d_in[8];
    const float *wih2_0 = (const float*)d_in[9],  *whh2_0 = (const float*)d_in[10];
    const float *bih2_0 = (const float*)d_in[11], *bhh2_0 = (const float*)d_in[12];
    const float *wih2_1 = (const float*)d_in[13], *whh2_1 = (const float*)d_in[14];
    const float *bih2_1 = (const float*)d_in[15], *bhh2_1 = (const float*)d_in[16];
    const float *wa = (const float*)d_in[17];
    const float *wc = (const float*)d_in[19], *bc = (const float*)d_in[20];
    const float *wo = (const float*)d_in[21], *bo = (const float*)d_in[22];

    gru_l0_kernel<<<2 * SCTAS, TPB>>>(x, wih1_0, whh1_0, bih1_0, bhh1_0,
                                      wih2_0, whh2_0, bih2_0, bhh2_0);
    gi_kernel<<<2 * SCTAS, TPB>>>(wih1_1, bih1_1, wih2_1, bih2_1);
    gru_l1_kernel<<<2 * SCTAS, TPB>>>(whh1_1, bhh1_1, whh2_1, bhh2_1);
    sp_kernel<<<2 * BB, 256>>>(wa);
    attend_kernel<<<2 * BB, 256>>>(wc, bc);
    final_kernel<<<(BB * LL) / 8, 256>>>(wo, bo, (float*)d_out);
}